// round 1
// baseline (speedup 1.0000x reference)
#include <cuda_runtime.h>
#include <math.h>

#define TB 16384      // batch
#define TD 512        // dim (in = hid = out)
#define TE 8          // experts
#define LOG100 4.605170185988091f

// ---------------- device scratch (no allocations allowed) ----------------
__device__ int   g_cnt[TE];
__device__ int   g_list[TE * TB];
__device__ float g_wt[TE * TB];
__device__ float g_imp[TE];
__device__ float g_vq[1];
__device__ float g_aux[2];

// ---------------- packed f32x2 helpers (FFMA2) ----------------
__device__ __forceinline__ unsigned long long ffma2u(unsigned long long a,
                                                     unsigned long long b,
                                                     unsigned long long c) {
    unsigned long long d;
    asm("fma.rn.f32x2 %0, %1, %2, %3;" : "=l"(d) : "l"(a), "l"(b), "l"(c));
    return d;
}
__device__ __forceinline__ unsigned long long pack2(float x, float y) {
    unsigned long long r;
    asm("mov.b64 %0, {%1, %2};" : "=l"(r) : "f"(x), "f"(y));
    return r;
}
__device__ __forceinline__ float2 unpack2(unsigned long long v) {
    float2 r;
    asm("mov.b64 {%0, %1}, %2;" : "=f"(r.x), "=f"(r.y) : "l"(v));
    return r;
}

// ---------------- zero kernels ----------------
__global__ void zero_out_kernel(float* __restrict__ p, int n) {
    int i = blockIdx.x * blockDim.x + threadIdx.x;
    int stride = gridDim.x * blockDim.x;
    for (; i < n; i += stride) p[i] = 0.0f;
}

__global__ void zero_small_kernel() {
    int t = threadIdx.x;
    if (t < TE) { g_cnt[t] = 0; g_imp[t] = 0.0f; }
    if (t == 0) g_vq[0] = 0.0f;
}

// ---------------- router: dists, top-2, softmax, scatter lists + aux accum --
__global__ void __launch_bounds__(256) router_kernel(const float* __restrict__ x,
                                                     const float* __restrict__ rm,
                                                     int relu_in) {
    __shared__ float s_rm[TE][TD];
    __shared__ float s_rmn[TE];
    const int tid = threadIdx.x;
    for (int i = tid; i < TE * TD; i += 256) s_rm[i >> 9][i & 511] = rm[i];
    __syncthreads();

    const int w = tid >> 5;
    const int lane = tid & 31;

    // rm row norms (warp w handles expert w)
    {
        float s = 0.0f;
        #pragma unroll
        for (int j = 0; j < 16; j++) { float v = s_rm[w][lane + 32 * j]; s += v * v; }
        #pragma unroll
        for (int o = 16; o > 0; o >>= 1) s += __shfl_xor_sync(0xffffffffu, s, o);
        if (lane == 0) s_rmn[w] = fmaxf(sqrtf(s), 1e-12f);
    }
    __syncthreads();

    const int b = blockIdx.x * 8 + w;
    float xx = 0.0f, dot[TE];
    #pragma unroll
    for (int e = 0; e < TE; e++) dot[e] = 0.0f;
    const float* xr = x + (size_t)b * TD;
    #pragma unroll
    for (int j = 0; j < 16; j++) {
        float xv = xr[lane + 32 * j];
        if (relu_in) xv = fmaxf(xv, 0.0f);
        xx = fmaf(xv, xv, xx);
        #pragma unroll
        for (int e = 0; e < TE; e++) dot[e] = fmaf(xv, s_rm[e][lane + 32 * j], dot[e]);
    }
    #pragma unroll
    for (int o = 16; o > 0; o >>= 1) {
        xx += __shfl_xor_sync(0xffffffffu, xx, o);
        #pragma unroll
        for (int e = 0; e < TE; e++) dot[e] += __shfl_xor_sync(0xffffffffu, dot[e], o);
    }

    if (lane == 0) {
        float xn = fmaxf(sqrtf(xx), 1e-12f);
        float d[TE];
        #pragma unroll
        for (int e = 0; e < TE; e++) d[e] = dot[e] / (xn * s_rmn[e]);

        int i0 = 0; float v0 = d[0];
        #pragma unroll
        for (int e = 1; e < TE; e++) if (d[e] > v0) { v0 = d[e]; i0 = e; }
        int i1 = (i0 == 0) ? 1 : 0; float v1 = d[i1];
        #pragma unroll
        for (int e = 0; e < TE; e++) {
            if (e != i0 && d[e] > v1) { v1 = d[e]; i1 = e; }
        }
        // softmax over (v0, v1), v0 = max
        float e1 = expf(v1 - v0);
        float inv = 1.0f / (1.0f + e1);
        float tv0 = inv;
        float tv1 = e1 * inv;

        int p0 = atomicAdd(&g_cnt[i0], 1);
        g_list[i0 * TB + p0] = b;
        g_wt[i0 * TB + p0] = tv0;
        int p1 = atomicAdd(&g_cnt[i1], 1);
        g_list[i1 * TB + p1] = b;
        g_wt[i1 * TB + p1] = tv1;

        atomicAdd(&g_imp[i0], tv0);
        atomicAdd(&g_imp[i1], tv1);
        atomicAdd(&g_vq[0], -(tv0 * v0 + tv1 * v1));
    }
}

// ---------------- aux finalize per layer ----------------
__global__ void finalize_kernel(int layer) {
    if (threadIdx.x == 0 && blockIdx.x == 0) {
        float m = 0.0f;
        for (int e = 0; e < TE; e++) m += g_imp[e];
        m *= (1.0f / TE);
        float var = 0.0f;
        for (int e = 0; e < TE; e++) { float dd = g_imp[e] - m; var += dd * dd; }
        var *= (1.0f / (TE - 1));
        float lb = var / (m * m + 1e-10f);
        g_aux[layer] = 0.05f * (g_vq[0] * (1.0f / TB)) + 0.01f * lb;
    }
}

// ---------------- grouped gather-GEMM-scatter (128x128x8 tile, FFMA2) -------
__global__ void __launch_bounds__(256, 2) gemm_kernel(
    const float* __restrict__ X, const float* __restrict__ W,
    const float* __restrict__ bias, const float* __restrict__ ca,
    const float* __restrict__ temp, float* __restrict__ out, int relu_in) {
    const int e = blockIdx.z;
    const int cnt = g_cnt[e];
    const int row0 = blockIdx.y * 128;
    if (row0 >= cnt) return;
    const int col0 = blockIdx.x * 128;

    __shared__ float As[8][128];
    __shared__ float Bs[8][128];
    __shared__ int s_row[128];

    const int tid = threadIdx.x;
    if (tid < 128) {
        int r = row0 + tid;
        s_row[tid] = (r < cnt) ? g_list[e * TB + r] : 0;
    }
    __syncthreads();

    // loader mapping: conflict-free smem stores
    const int lr = tid & 127;          // row within tile / W output col within tile
    const int lh = (tid >> 7) << 2;    // 0 or 4 (which half of the 8-wide k chunk)
    const int arow = s_row[lr];
    const float* aptr = X + (size_t)arow * TD + lh;
    const float* bptr = W + (size_t)e * TD * TD + (size_t)(col0 + lr) * TD + lh;

    // compute mapping: 8x8 micro-tile (2x2 blocks of 4x4)
    const int tx = tid & 15;
    const int ty = tid >> 4;
    const int m0 = tx * 4;
    const int n0 = ty * 4;

    unsigned long long acc[2][4][2][2];
    #pragma unroll
    for (int a = 0; a < 2; a++)
        #pragma unroll
        for (int bb = 0; bb < 4; bb++)
            #pragma unroll
            for (int c = 0; c < 2; c++) {
                acc[a][bb][c][0] = 0ull;
                acc[a][bb][c][1] = 0ull;
            }

    for (int k0 = 0; k0 < TD; k0 += 8) {
        float4 av = *(const float4*)(aptr + k0);
        if (relu_in) {
            av.x = fmaxf(av.x, 0.0f); av.y = fmaxf(av.y, 0.0f);
            av.z = fmaxf(av.z, 0.0f); av.w = fmaxf(av.w, 0.0f);
        }
        float4 bv = *(const float4*)(bptr + k0);
        __syncthreads();
        As[lh + 0][lr] = av.x; As[lh + 1][lr] = av.y;
        As[lh + 2][lr] = av.z; As[lh + 3][lr] = av.w;
        Bs[lh + 0][lr] = bv.x; Bs[lh + 1][lr] = bv.y;
        Bs[lh + 2][lr] = bv.z; Bs[lh + 3][lr] = bv.w;
        __syncthreads();

        #pragma unroll
        for (int k = 0; k < 8; k++) {
            float4 a0 = *(const float4*)&As[k][m0];
            float4 a1 = *(const float4*)&As[k][m0 + 64];
            const unsigned long long* bp = (const unsigned long long*)&Bs[k][0];
            unsigned long long bq[2][2];
            bq[0][0] = bp[(n0 >> 1) + 0];
            bq[0][1] = bp[(n0 >> 1) + 1];
            bq[1][0] = bp[((n0 + 64) >> 1) + 0];
            bq[1][1] = bp[((n0 + 64) >> 1) + 1];
            float am[2][4] = {{a0.x, a0.y, a0.z, a0.w}, {a1.x, a1.y, a1.z, a1.w}};
            #pragma unroll
            for (int mh = 0; mh < 2; mh++)
                #pragma unroll
                for (int ml = 0; ml < 4; ml++) {
                    unsigned long long ad = pack2(am[mh][ml], am[mh][ml]);
                    #pragma unroll
                    for (int nh = 0; nh < 2; nh++) {
                        acc[mh][ml][nh][0] = ffma2u(ad, bq[nh][0], acc[mh][ml][nh][0]);
                        acc[mh][ml][nh][1] = ffma2u(ad, bq[nh][1], acc[mh][ml][nh][1]);
                    }
                }
        }
    }

    // epilogue: out[tok, col] += temp_s * tv * (acc * inp_att + bias)
    const float temp_s = expf(fminf(temp[0], LOG100));
    const float ia = expf(fminf(ca[e], LOG100));
    #pragma unroll
    for (int mh = 0; mh < 2; mh++) {
        #pragma unroll
        for (int ml = 0; ml < 4; ml++) {
            const int lm = m0 + mh * 64 + ml;
            const int r = row0 + lm;
            if (r < cnt) {
                const int tok = s_row[lm];
                const float wt = g_wt[e * TB + r] * temp_s;
                float* orow = out + (size_t)tok * TD;
                #pragma unroll
                for (int nh = 0; nh < 2; nh++) {
                    #pragma unroll
                    for (int np = 0; np < 2; np++) {
                        const int col = col0 + n0 + nh * 64 + np * 2;
                        float2 v = unpack2(acc[mh][ml][nh][np]);
                        atomicAdd(&orow[col + 0], wt * (v.x * ia + bias[e * TD + col + 0]));
                        atomicAdd(&orow[col + 1], wt * (v.y * ia + bias[e * TD + col + 1]));
                    }
                }
            }
        }
    }
}

// ---------------- final aux write ----------------
__global__ void write_aux_kernel(float* __restrict__ out) {
    if (threadIdx.x == 0 && blockIdx.x == 0)
        out[(size_t)2 * TB * TD] = g_aux[0] + g_aux[1];
}

// ---------------- launch ----------------
extern "C" void kernel_launch(void* const* d_in, const int* in_sizes, int n_in,
                              void* d_out, int out_size) {
    const float* x   = (const float*)d_in[0];
    const float* rm0 = (const float*)d_in[1];
    const float* W0  = (const float*)d_in[2];
    const float* b0  = (const float*)d_in[3];
    const float* t0  = (const float*)d_in[4];
    const float* ca0 = (const float*)d_in[5];
    const float* rm1 = (const float*)d_in[6];
    const float* W1  = (const float*)d_in[7];
    const float* b1  = (const float*)d_in[8];
    const float* t1  = (const float*)d_in[9];
    const float* ca1 = (const float*)d_in[10];

    float* out = (float*)d_out;
    float* h0 = out;                      // h_emb region
    float* h1 = out + (size_t)TB * TD;    // h1 region

    zero_out_kernel<<<4096, 256>>>(out, 2 * TB * TD);

    // ---- layer 0 ----
    zero_small_kernel<<<1, 32>>>();
    router_kernel<<<TB / 8, 256>>>(x, rm0, 0);
    finalize_kernel<<<1, 32>>>(0);
    dim3 gg(TD / 128, TB / 128, TE);
    gemm_kernel<<<gg, 256>>>(x, W0, b0, ca0, t0, h0, 0);

    // ---- layer 1 (input = relu(h0), applied on the fly) ----
    zero_small_kernel<<<1, 32>>>();
    router_kernel<<<TB / 8, 256>>>(h0, rm1, 1);
    finalize_kernel<<<1, 32>>>(1);
    gemm_kernel<<<gg, 256>>>(h0, W1, b1, ca1, t1, h1, 1);

    write_aux_kernel<<<1, 1>>>(out);
}

// round 3
// speedup vs baseline: 1.3812x; 1.3812x over previous
#include <cuda_runtime.h>
#include <cuda_bf16.h>
#include <math.h>
#include <stdint.h>

#define TB 16384      // batch
#define TD 512        // dim (in = hid = out)
#define TE 8          // experts
#define LOG100 4.605170185988091f

// ---------------- device scratch (no allocations allowed) ----------------
__device__ int   g_cnt[TE];
__device__ int   g_list[TE * TB];
__device__ float g_wt[TE * TB];
__device__ float g_imp[TE];
__device__ float g_vq[1];
__device__ float g_aux[2];

// bf16 split buffers: X (or relu(h0)) and W per layer
__device__ __nv_bfloat16 g_ah[TB * TD];
__device__ __nv_bfloat16 g_al[TB * TD];
__device__ __nv_bfloat16 g_bh[TE * TD * TD];
__device__ __nv_bfloat16 g_bl[TE * TD * TD];

// ---------------- helpers ----------------
__device__ __forceinline__ uint32_t smem_u32(const void* p) {
    uint32_t a;
    asm("{ .reg .u64 t; cvta.to.shared.u64 t, %1; cvt.u32.u64 %0, t; }" : "=r"(a) : "l"(p));
    return a;
}
__device__ __forceinline__ uint32_t swz128(uint32_t off) {
    return off ^ ((off >> 3) & 0x70);
}
__device__ __forceinline__ void cp16(uint32_t saddr, const void* gaddr) {
    asm volatile("cp.async.cg.shared.global [%0], [%1], 16;" :: "r"(saddr), "l"(gaddr));
}
__device__ __forceinline__ void cp_commit() {
    asm volatile("cp.async.commit_group;");
}
__device__ __forceinline__ void cp_wait1() {
    asm volatile("cp.async.wait_group 1;");
}
__device__ __forceinline__ void cp_wait0() {
    asm volatile("cp.async.wait_group 0;");
}
__device__ __forceinline__ void ldsm_x4(uint32_t& r0, uint32_t& r1, uint32_t& r2,
                                        uint32_t& r3, uint32_t addr) {
    asm volatile("ldmatrix.sync.aligned.m8n8.x4.shared.b16 {%0,%1,%2,%3}, [%4];"
                 : "=r"(r0), "=r"(r1), "=r"(r2), "=r"(r3) : "r"(addr));
}
__device__ __forceinline__ void mma_bf16(float& c0, float& c1, float& c2, float& c3,
                                         uint32_t a0, uint32_t a1, uint32_t a2, uint32_t a3,
                                         uint32_t b0, uint32_t b1) {
    asm volatile(
        "mma.sync.aligned.m16n8k16.row.col.f32.bf16.bf16.f32 "
        "{%0,%1,%2,%3}, {%4,%5,%6,%7}, {%8,%9}, {%0,%1,%2,%3};"
        : "+f"(c0), "+f"(c1), "+f"(c2), "+f"(c3)
        : "r"(a0), "r"(a1), "r"(a2), "r"(a3), "r"(b0), "r"(b1));
}

// ---------------- zero kernels ----------------
__global__ void zero_out_kernel(float4* __restrict__ p, int n4) {
    int i = blockIdx.x * blockDim.x + threadIdx.x;
    int stride = gridDim.x * blockDim.x;
    float4 z = make_float4(0.f, 0.f, 0.f, 0.f);
    for (; i < n4; i += stride) p[i] = z;
}

__global__ void zero_small_kernel() {
    int t = threadIdx.x;
    if (t < TE) { g_cnt[t] = 0; g_imp[t] = 0.0f; }
    if (t == 0) g_vq[0] = 0.0f;
}

// ---------------- bf16 split conversion ----------------
__global__ void __launch_bounds__(256) conv_split_kernel(
    const float4* __restrict__ src, __nv_bfloat162* __restrict__ hi,
    __nv_bfloat162* __restrict__ lo, int n4, int relu) {
    int i = blockIdx.x * blockDim.x + threadIdx.x;
    if (i >= n4) return;
    float4 a = src[i];
    if (relu) {
        a.x = fmaxf(a.x, 0.f); a.y = fmaxf(a.y, 0.f);
        a.z = fmaxf(a.z, 0.f); a.w = fmaxf(a.w, 0.f);
    }
    __nv_bfloat16 hx = __float2bfloat16(a.x), hy = __float2bfloat16(a.y);
    __nv_bfloat16 hz = __float2bfloat16(a.z), hw = __float2bfloat16(a.w);
    __nv_bfloat16 lx = __float2bfloat16(a.x - __bfloat162float(hx));
    __nv_bfloat16 ly = __float2bfloat16(a.y - __bfloat162float(hy));
    __nv_bfloat16 lz = __float2bfloat16(a.z - __bfloat162float(hz));
    __nv_bfloat16 lw = __float2bfloat16(a.w - __bfloat162float(hw));
    hi[2 * i]     = __nv_bfloat162(hx, hy);
    hi[2 * i + 1] = __nv_bfloat162(hz, hw);
    lo[2 * i]     = __nv_bfloat162(lx, ly);
    lo[2 * i + 1] = __nv_bfloat162(lz, lw);
}

// ---------------- router ----------------
__global__ void __launch_bounds__(256) router_kernel(const float* __restrict__ x,
                                                     const float* __restrict__ rm,
                                                     int relu_in) {
    __shared__ float s_rm[TE][TD];
    __shared__ float s_rmn[TE];
    const int tid = threadIdx.x;
    for (int i = tid; i < TE * TD; i += 256) s_rm[i >> 9][i & 511] = rm[i];
    __syncthreads();

    const int w = tid >> 5;
    const int lane = tid & 31;

    {
        float s = 0.0f;
        #pragma unroll
        for (int j = 0; j < 16; j++) { float v = s_rm[w][lane + 32 * j]; s += v * v; }
        #pragma unroll
        for (int o = 16; o > 0; o >>= 1) s += __shfl_xor_sync(0xffffffffu, s, o);
        if (lane == 0) s_rmn[w] = fmaxf(sqrtf(s), 1e-12f);
    }
    __syncthreads();

    const int b = blockIdx.x * 8 + w;
    float xx = 0.0f, dot[TE];
    #pragma unroll
    for (int e = 0; e < TE; e++) dot[e] = 0.0f;
    const float* xr = x + (size_t)b * TD;
    #pragma unroll
    for (int j = 0; j < 16; j++) {
        float xv = xr[lane + 32 * j];
        if (relu_in) xv = fmaxf(xv, 0.0f);
        xx = fmaf(xv, xv, xx);
        #pragma unroll
        for (int e = 0; e < TE; e++) dot[e] = fmaf(xv, s_rm[e][lane + 32 * j], dot[e]);
    }
    #pragma unroll
    for (int o = 16; o > 0; o >>= 1) {
        xx += __shfl_xor_sync(0xffffffffu, xx, o);
        #pragma unroll
        for (int e = 0; e < TE; e++) dot[e] += __shfl_xor_sync(0xffffffffu, dot[e], o);
    }

    if (lane == 0) {
        float xn = fmaxf(sqrtf(xx), 1e-12f);
        float d[TE];
        #pragma unroll
        for (int e = 0; e < TE; e++) d[e] = dot[e] / (xn * s_rmn[e]);

        int i0 = 0; float v0 = d[0];
        #pragma unroll
        for (int e = 1; e < TE; e++) if (d[e] > v0) { v0 = d[e]; i0 = e; }
        int i1 = (i0 == 0) ? 1 : 0; float v1 = d[i1];
        #pragma unroll
        for (int e = 0; e < TE; e++) {
            if (e != i0 && d[e] > v1) { v1 = d[e]; i1 = e; }
        }
        float e1 = expf(v1 - v0);
        float inv = 1.0f / (1.0f + e1);
        float tv0 = inv;
        float tv1 = e1 * inv;

        int p0 = atomicAdd(&g_cnt[i0], 1);
        g_list[i0 * TB + p0] = b;
        g_wt[i0 * TB + p0] = tv0;
        int p1 = atomicAdd(&g_cnt[i1], 1);
        g_list[i1 * TB + p1] = b;
        g_wt[i1 * TB + p1] = tv1;

        atomicAdd(&g_imp[i0], tv0);
        atomicAdd(&g_imp[i1], tv1);
        atomicAdd(&g_vq[0], -(tv0 * v0 + tv1 * v1));
    }
}

// ---------------- aux finalize ----------------
__global__ void finalize_kernel(int layer) {
    if (threadIdx.x == 0 && blockIdx.x == 0) {
        float m = 0.0f;
        for (int e = 0; e < TE; e++) m += g_imp[e];
        m *= (1.0f / TE);
        float var = 0.0f;
        for (int e = 0; e < TE; e++) { float dd = g_imp[e] - m; var += dd * dd; }
        var *= (1.0f / (TE - 1));
        float lb = var / (m * m + 1e-10f);
        g_aux[layer] = 0.05f * (g_vq[0] * (1.0f / TB)) + 0.01f * lb;
    }
}

// ---------------- mma.sync grouped gather-GEMM-scatter ----------------
// Block: 128(M) x 128(N), 512 threads = 16 warps (4x4), warp tile 32x32.
// K chunks of 64, double-buffered cp.async, bf16 3-term split, fp32 accum.
// SMEM: [16..528) s_row; tiles at 1024: per buf {Ah,Al,Bh,Bl} x 16KB = 64KB, x2.
#define GEMM_SMEM_BYTES (1024 + 2 * 4 * 16384)

__global__ void __launch_bounds__(512, 1)
gemm_mma_kernel(const float* __restrict__ bias, const float* __restrict__ ca,
                const float* __restrict__ temp, float* __restrict__ out) {
    const int e = blockIdx.z;
    const int cnt = g_cnt[e];
    const int row0 = blockIdx.y * 128;
    if (row0 >= cnt) return;
    const int col0 = blockIdx.x * 128;

    extern __shared__ char smem[];
    const uint32_t sbase = smem_u32(smem);
    int* s_row = (int*)(smem + 16);
    const int tid = threadIdx.x;

    if (tid < 128) {
        int r = row0 + tid;
        s_row[tid] = (r < cnt) ? g_list[e * TB + r] : 0;
    }
    __syncthreads();

    // ---- loader mapping: 512 threads = 4 tiles x 128 rows ----
    const int lt = tid >> 7;       // 0:Ah 1:Al 2:Bh 3:Bl
    const int lr = tid & 127;
    const __nv_bfloat16* lsrc;
    if (lt == 0)      lsrc = g_ah + (size_t)s_row[lr] * TD;
    else if (lt == 1) lsrc = g_al + (size_t)s_row[lr] * TD;
    else if (lt == 2) lsrc = g_bh + ((size_t)e * TD + col0 + lr) * TD;
    else              lsrc = g_bl + ((size_t)e * TD + col0 + lr) * TD;
    uint32_t lsw[8];
    #pragma unroll
    for (int j = 0; j < 8; j++) lsw[j] = swz128(lr * 128 + j * 16);
    const uint32_t ltile = sbase + 1024 + lt * 16384;

    // issue chunk c into buffer (c&1)
    auto issue = [&](int c) {
        const uint32_t sb = ltile + (c & 1) * 65536;
        const char* gp = (const char*)lsrc + c * 128;  // 64 bf16 per chunk
        #pragma unroll
        for (int j = 0; j < 8; j++) cp16(sb + lsw[j], gp + j * 16);
        cp_commit();
    };

    // ---- compute mapping ----
    const int warp = tid >> 5;
    const int lane = tid & 31;
    const int m0w = (warp >> 2) * 32;   // warp row
    const int n0w = (warp & 3) * 32;    // warp col

    // ldmatrix source offsets (within a 128x64 bf16 tile, 128B rows)
    // A frag (m16k16): row = m0w + mi*16 + (lane&15), k = kk + (lane>>4)*8
    const int a_r = lane & 15;
    const int a_k = (lane >> 4) << 3;
    // B frag pair (x4 covers 2 n-frags): n = nbase + ((sel>>1)<<3)+idx, k = kk + (sel&1)*8
    const int b_idx = lane & 7;
    const int b_sel = lane >> 3;
    const int b_n = ((b_sel >> 1) << 3) + b_idx;
    const int b_k = (b_sel & 1) << 3;

    float acc[2][4][4];
    #pragma unroll
    for (int mi = 0; mi < 2; mi++)
        #pragma unroll
        for (int ni = 0; ni < 4; ni++)
            #pragma unroll
            for (int q = 0; q < 4; q++) acc[mi][ni][q] = 0.0f;

    issue(0);

    for (int c = 0; c < 8; c++) {
        if (c + 1 < 8) { issue(c + 1); cp_wait1(); }
        else cp_wait0();
        __syncthreads();

        const uint32_t base = sbase + 1024 + (c & 1) * 65536;
        const uint32_t tAh = base, tAl = base + 16384;
        const uint32_t tBh = base + 32768, tBl = base + 49152;

        #pragma unroll
        for (int ks = 0; ks < 4; ks++) {
            const int kk = ks * 16;
            uint32_t ah[2][4], al[2][4], bh[2][4], bl[2][4];
            #pragma unroll
            for (int mi = 0; mi < 2; mi++) {
                uint32_t off = swz128((m0w + mi * 16 + a_r) * 128 + (kk + a_k) * 2);
                ldsm_x4(ah[mi][0], ah[mi][1], ah[mi][2], ah[mi][3], tAh + off);
                ldsm_x4(al[mi][0], al[mi][1], al[mi][2], al[mi][3], tAl + off);
            }
            #pragma unroll
            for (int hb = 0; hb < 2; hb++) {
                uint32_t off = swz128((n0w + hb * 16 + b_n) * 128 + (kk + b_k) * 2);
                ldsm_x4(bh[hb][0], bh[hb][1], bh[hb][2], bh[hb][3], tBh + off);
                ldsm_x4(bl[hb][0], bl[hb][1], bl[hb][2], bl[hb][3], tBl + off);
            }
            #pragma unroll
            for (int mi = 0; mi < 2; mi++)
                #pragma unroll
                for (int ni = 0; ni < 4; ni++) {
                    uint32_t b0h = bh[ni >> 1][(ni & 1) * 2];
                    uint32_t b1h = bh[ni >> 1][(ni & 1) * 2 + 1];
                    uint32_t b0l = bl[ni >> 1][(ni & 1) * 2];
                    uint32_t b1l = bl[ni >> 1][(ni & 1) * 2 + 1];
                    float* cc = acc[mi][ni];
                    mma_bf16(cc[0], cc[1], cc[2], cc[3],
                             ah[mi][0], ah[mi][1], ah[mi][2], ah[mi][3], b0h, b1h);
                    mma_bf16(cc[0], cc[1], cc[2], cc[3],
                             ah[mi][0], ah[mi][1], ah[mi][2], ah[mi][3], b0l, b1l);
                    mma_bf16(cc[0], cc[1], cc[2], cc[3],
                             al[mi][0], al[mi][1], al[mi][2], al[mi][3], b0h, b1h);
                }
        }
        __syncthreads();
    }

    // ---- epilogue: out[tok, col] += temp_s * tv * (acc * inp_att + bias) ----
    const float temp_s = expf(fminf(temp[0], LOG100));
    const float ia = expf(fminf(ca[e], LOG100));
    const int cbase = col0 + n0w + (lane & 3) * 2;
    #pragma unroll
    for (int mi = 0; mi < 2; mi++) {
        #pragma unroll
        for (int half = 0; half < 2; half++) {
            const int rloc = m0w + mi * 16 + (lane >> 2) + half * 8;
            const int r = row0 + rloc;
            if (r < cnt) {
                const int tok = s_row[rloc];
                const float wt = g_wt[e * TB + r] * temp_s;
                float* orow = out + (size_t)tok * TD;
                const float* brow = bias + e * TD;
                #pragma unroll
                for (int ni = 0; ni < 4; ni++) {
                    const int col = cbase + ni * 8;
                    const float v0 = acc[mi][ni][half * 2 + 0];
                    const float v1 = acc[mi][ni][half * 2 + 1];
                    atomicAdd(orow + col,     wt * (v0 * ia + brow[col]));
                    atomicAdd(orow + col + 1, wt * (v1 * ia + brow[col + 1]));
                }
            }
        }
    }
}

// ---------------- final aux write ----------------
__global__ void write_aux_kernel(float* __restrict__ out) {
    if (threadIdx.x == 0 && blockIdx.x == 0)
        out[(size_t)2 * TB * TD] = g_aux[0] + g_aux[1];
}

// ---------------- launch ----------------
extern "C" void kernel_launch(void* const* d_in, const int* in_sizes, int n_in,
                              void* d_out, int out_size) {
    const float* x   = (const float*)d_in[0];
    const float* rm0 = (const float*)d_in[1];
    const float* W0  = (const float*)d_in[2];
    const float* b0  = (const float*)d_in[3];
    const float* t0  = (const float*)d_in[4];
    const float* ca0 = (const float*)d_in[5];
    const float* rm1 = (const float*)d_in[6];
    const float* W1  = (const float*)d_in[7];
    const float* b1  = (const float*)d_in[8];
    const float* t1  = (const float*)d_in[9];
    const float* ca1 = (const float*)d_in[10];

    float* out = (float*)d_out;
    float* h0 = out;                      // h_emb region
    float* h1 = out + (size_t)TB * TD;    // h1 region

    cudaFuncSetAttribute(gemm_mma_kernel,
                         cudaFuncAttributeMaxDynamicSharedMemorySize,
                         GEMM_SMEM_BYTES);

    __nv_bfloat16* ah = nullptr, *al = nullptr, *bh = nullptr, *bl = nullptr;
    cudaGetSymbolAddress((void**)&ah, g_ah);
    cudaGetSymbolAddress((void**)&al, g_al);
    cudaGetSymbolAddress((void**)&bh, g_bh);
    cudaGetSymbolAddress((void**)&bl, g_bl);

    const int nX4 = TB * TD / 4;
    const int nW4 = TE * TD * TD / 4;

    zero_out_kernel<<<2048, 256>>>((float4*)out, 2 * TB * TD / 4);

    dim3 gg(TD / 128, TB / 128, TE);

    // ---- layer 0 ----
    zero_small_kernel<<<1, 32>>>();
    router_kernel<<<TB / 8, 256>>>(x, rm0, 0);
    finalize_kernel<<<1, 32>>>(0);
    conv_split_kernel<<<(nX4 + 255) / 256, 256>>>((const float4*)x,
        (__nv_bfloat162*)ah, (__nv_bfloat162*)al, nX4, 0);
    conv_split_kernel<<<(nW4 + 255) / 256, 256>>>((const float4*)W0,
        (__nv_bfloat162*)bh, (__nv_bfloat162*)bl, nW4, 0);
    gemm_mma_kernel<<<gg, 512, GEMM_SMEM_BYTES>>>(b0, ca0, t0, h0);

    // ---- layer 1 (input = relu(h0)) ----
    zero_small_kernel<<<1, 32>>>();
    router_kernel<<<TB / 8, 256>>>(h0, rm1, 1);
    finalize_kernel<<<1, 32>>>(1);
    conv_split_kernel<<<(nX4 + 255) / 256, 256>>>((const float4*)h0,
        (__nv_bfloat162*)ah, (__nv_bfloat162*)al, nX4, 1);
    conv_split_kernel<<<(nW4 + 255) / 256, 256>>>((const float4*)W1,
        (__nv_bfloat162*)bh, (__nv_bfloat162*)bl, nW4, 0);
    gemm_mma_kernel<<<gg, 512, GEMM_SMEM_BYTES>>>(b1, ca1, t1, h1);

    write_aux_kernel<<<1, 1>>>(out);
}

// round 4
// speedup vs baseline: 1.4169x; 1.0259x over previous
#include <cuda_runtime.h>
#include <cuda_bf16.h>
#include <math.h>
#include <stdint.h>

#define TB 16384      // batch
#define TD 512        // dim (in = hid = out)
#define TE 8          // experts
#define LOG100 4.605170185988091f

// ---------------- device scratch (no allocations allowed) ----------------
__device__ int   g_cnt[TE];
__device__ int   g_base[TE];
__device__ int   g_list[TE * TB];      // expert -> token
__device__ float g_imp[TE];
__device__ float g_vq[1];
__device__ float g_aux[2];
// per-token routing meta
__device__ int   g_te0[TB], g_te1[TB];
__device__ int   g_tp0[TB], g_tp1[TB];
__device__ float g_tv0[TB], g_tv1[TB];
// staging: raw GEMM accumulators, rows ordered by (expert, position)
__device__ float g_y[2 * TB * TD];
// bf16 split buffers
__device__ __nv_bfloat16 g_ah[TB * TD];
__device__ __nv_bfloat16 g_al[TB * TD];
__device__ __nv_bfloat16 g_bh[TE * TD * TD];
__device__ __nv_bfloat16 g_bl[TE * TD * TD];

// ---------------- helpers ----------------
__device__ __forceinline__ uint32_t smem_u32(const void* p) {
    uint32_t a;
    asm("{ .reg .u64 t; cvta.to.shared.u64 t, %1; cvt.u32.u64 %0, t; }" : "=r"(a) : "l"(p));
    return a;
}
__device__ __forceinline__ uint32_t swz128(uint32_t off) {
    return off ^ ((off >> 3) & 0x70);
}
__device__ __forceinline__ void cp16(uint32_t saddr, const void* gaddr) {
    asm volatile("cp.async.cg.shared.global [%0], [%1], 16;" :: "r"(saddr), "l"(gaddr));
}
__device__ __forceinline__ void cp_commit() {
    asm volatile("cp.async.commit_group;");
}
__device__ __forceinline__ void cp_wait1() {
    asm volatile("cp.async.wait_group 1;");
}
__device__ __forceinline__ void cp_wait0() {
    asm volatile("cp.async.wait_group 0;");
}
__device__ __forceinline__ void ldsm_x4(uint32_t& r0, uint32_t& r1, uint32_t& r2,
                                        uint32_t& r3, uint32_t addr) {
    asm volatile("ldmatrix.sync.aligned.m8n8.x4.shared.b16 {%0,%1,%2,%3}, [%4];"
                 : "=r"(r0), "=r"(r1), "=r"(r2), "=r"(r3) : "r"(addr));
}
__device__ __forceinline__ void mma_bf16(float& c0, float& c1, float& c2, float& c3,
                                         uint32_t a0, uint32_t a1, uint32_t a2, uint32_t a3,
                                         uint32_t b0, uint32_t b1) {
    asm volatile(
        "mma.sync.aligned.m16n8k16.row.col.f32.bf16.bf16.f32 "
        "{%0,%1,%2,%3}, {%4,%5,%6,%7}, {%8,%9}, {%0,%1,%2,%3};"
        : "+f"(c0), "+f"(c1), "+f"(c2), "+f"(c3)
        : "r"(a0), "r"(a1), "r"(a2), "r"(a3), "r"(b0), "r"(b1));
}

// ---------------- small init ----------------
__global__ void zero_small_kernel() {
    int t = threadIdx.x;
    if (t < TE) { g_cnt[t] = 0; g_imp[t] = 0.0f; }
    if (t == 0) g_vq[0] = 0.0f;
}

// ---------------- bf16 split conversion (X layer0 and W) ----------------
__global__ void __launch_bounds__(256) conv_split_kernel(
    const float4* __restrict__ src, __nv_bfloat162* __restrict__ hi,
    __nv_bfloat162* __restrict__ lo, int n4) {
    int i = blockIdx.x * blockDim.x + threadIdx.x;
    if (i >= n4) return;
    float4 a = src[i];
    __nv_bfloat16 hx = __float2bfloat16(a.x), hy = __float2bfloat16(a.y);
    __nv_bfloat16 hz = __float2bfloat16(a.z), hw = __float2bfloat16(a.w);
    __nv_bfloat16 lx = __float2bfloat16(a.x - __bfloat162float(hx));
    __nv_bfloat16 ly = __float2bfloat16(a.y - __bfloat162float(hy));
    __nv_bfloat16 lz = __float2bfloat16(a.z - __bfloat162float(hz));
    __nv_bfloat16 lw = __float2bfloat16(a.w - __bfloat162float(hw));
    hi[2 * i]     = __nv_bfloat162(hx, hy);
    hi[2 * i + 1] = __nv_bfloat162(hz, hw);
    lo[2 * i]     = __nv_bfloat162(lx, ly);
    lo[2 * i + 1] = __nv_bfloat162(lz, lw);
}

// ---------------- router ----------------
__global__ void __launch_bounds__(256) router_kernel(const float* __restrict__ x,
                                                     const float* __restrict__ rm,
                                                     int relu_in) {
    __shared__ float s_rm[TE][TD];
    __shared__ float s_rmn[TE];
    const int tid = threadIdx.x;
    for (int i = tid; i < TE * TD; i += 256) s_rm[i >> 9][i & 511] = rm[i];
    __syncthreads();

    const int w = tid >> 5;
    const int lane = tid & 31;

    {
        float s = 0.0f;
        #pragma unroll
        for (int j = 0; j < 16; j++) { float v = s_rm[w][lane + 32 * j]; s += v * v; }
        #pragma unroll
        for (int o = 16; o > 0; o >>= 1) s += __shfl_xor_sync(0xffffffffu, s, o);
        if (lane == 0) s_rmn[w] = fmaxf(sqrtf(s), 1e-12f);
    }
    __syncthreads();

    const int b = blockIdx.x * 8 + w;
    float xx = 0.0f, dot[TE];
    #pragma unroll
    for (int e = 0; e < TE; e++) dot[e] = 0.0f;
    const float* xr = x + (size_t)b * TD;
    #pragma unroll
    for (int j = 0; j < 16; j++) {
        float xv = xr[lane + 32 * j];
        if (relu_in) xv = fmaxf(xv, 0.0f);
        xx = fmaf(xv, xv, xx);
        #pragma unroll
        for (int e = 0; e < TE; e++) dot[e] = fmaf(xv, s_rm[e][lane + 32 * j], dot[e]);
    }
    #pragma unroll
    for (int o = 16; o > 0; o >>= 1) {
        xx += __shfl_xor_sync(0xffffffffu, xx, o);
        #pragma unroll
        for (int e = 0; e < TE; e++) dot[e] += __shfl_xor_sync(0xffffffffu, dot[e], o);
    }

    if (lane == 0) {
        float xn = fmaxf(sqrtf(xx), 1e-12f);
        float d[TE];
        #pragma unroll
        for (int e = 0; e < TE; e++) d[e] = dot[e] / (xn * s_rmn[e]);

        int i0 = 0; float v0 = d[0];
        #pragma unroll
        for (int e = 1; e < TE; e++) if (d[e] > v0) { v0 = d[e]; i0 = e; }
        int i1 = (i0 == 0) ? 1 : 0; float v1 = d[i1];
        #pragma unroll
        for (int e = 0; e < TE; e++) {
            if (e != i0 && d[e] > v1) { v1 = d[e]; i1 = e; }
        }
        float e1 = expf(v1 - v0);
        float inv = 1.0f / (1.0f + e1);
        float tv0 = inv;
        float tv1 = e1 * inv;

        int p0 = atomicAdd(&g_cnt[i0], 1);
        g_list[i0 * TB + p0] = b;
        int p1 = atomicAdd(&g_cnt[i1], 1);
        g_list[i1 * TB + p1] = b;

        g_te0[b] = i0; g_te1[b] = i1;
        g_tp0[b] = p0; g_tp1[b] = p1;
        g_tv0[b] = tv0; g_tv1[b] = tv1;

        atomicAdd(&g_imp[i0], tv0);
        atomicAdd(&g_imp[i1], tv1);
        atomicAdd(&g_vq[0], -(tv0 * v0 + tv1 * v1));
    }
}

// ---------------- aux finalize + base prefix ----------------
__global__ void finalize_kernel(int layer) {
    if (threadIdx.x == 0 && blockIdx.x == 0) {
        float m = 0.0f;
        for (int e = 0; e < TE; e++) m += g_imp[e];
        m *= (1.0f / TE);
        float var = 0.0f;
        for (int e = 0; e < TE; e++) { float dd = g_imp[e] - m; var += dd * dd; }
        var *= (1.0f / (TE - 1));
        float lb = var / (m * m + 1e-10f);
        g_aux[layer] = 0.05f * (g_vq[0] * (1.0f / TB)) + 0.01f * lb;
        int acc = 0;
        for (int e = 0; e < TE; e++) { g_base[e] = acc; acc += g_cnt[e]; }
    }
}

// ---------------- mma.sync grouped gather-GEMM -> staging ----------------
#define GEMM_SMEM_BYTES (1024 + 2 * 4 * 16384)

__global__ void __launch_bounds__(512, 1)
gemm_mma_kernel() {
    const int e = blockIdx.z;
    const int cnt = g_cnt[e];
    const int row0 = blockIdx.y * 128;
    if (row0 >= cnt) return;
    const int col0 = blockIdx.x * 128;
    const int ybase = g_base[e];

    extern __shared__ char smem[];
    const uint32_t sbase = smem_u32(smem);
    int* s_row = (int*)(smem + 16);
    const int tid = threadIdx.x;

    if (tid < 128) {
        int r = row0 + tid;
        s_row[tid] = (r < cnt) ? g_list[e * TB + r] : 0;
    }
    __syncthreads();

    // loader: 512 threads = 4 tiles x 128 rows
    const int lt = tid >> 7;       // 0:Ah 1:Al 2:Bh 3:Bl
    const int lr = tid & 127;
    const __nv_bfloat16* lsrc;
    if (lt == 0)      lsrc = g_ah + (size_t)s_row[lr] * TD;
    else if (lt == 1) lsrc = g_al + (size_t)s_row[lr] * TD;
    else if (lt == 2) lsrc = g_bh + ((size_t)e * TD + col0 + lr) * TD;
    else              lsrc = g_bl + ((size_t)e * TD + col0 + lr) * TD;
    uint32_t lsw[8];
    #pragma unroll
    for (int j = 0; j < 8; j++) lsw[j] = swz128(lr * 128 + j * 16);
    const uint32_t ltile = sbase + 1024 + lt * 16384;

    auto issue = [&](int c) {
        const uint32_t sb = ltile + (c & 1) * 65536;
        const char* gp = (const char*)lsrc + c * 128;
        #pragma unroll
        for (int j = 0; j < 8; j++) cp16(sb + lsw[j], gp + j * 16);
        cp_commit();
    };

    const int warp = tid >> 5;
    const int lane = tid & 31;
    const int m0w = (warp >> 2) * 32;
    const int n0w = (warp & 3) * 32;

    const int a_r = lane & 15;
    const int a_k = (lane >> 4) << 3;
    const int b_idx = lane & 7;
    const int b_sel = lane >> 3;
    const int b_n = ((b_sel >> 1) << 3) + b_idx;
    const int b_k = (b_sel & 1) << 3;

    float acc[2][4][4];
    #pragma unroll
    for (int mi = 0; mi < 2; mi++)
        #pragma unroll
        for (int ni = 0; ni < 4; ni++)
            #pragma unroll
            for (int q = 0; q < 4; q++) acc[mi][ni][q] = 0.0f;

    issue(0);

    for (int c = 0; c < 8; c++) {
        if (c + 1 < 8) { issue(c + 1); cp_wait1(); }
        else cp_wait0();
        __syncthreads();

        const uint32_t base = sbase + 1024 + (c & 1) * 65536;
        const uint32_t tAh = base, tAl = base + 16384;
        const uint32_t tBh = base + 32768, tBl = base + 49152;

        #pragma unroll
        for (int ks = 0; ks < 4; ks++) {
            const int kk = ks * 16;
            uint32_t ah[2][4], al[2][4], bh[2][4], bl[2][4];
            #pragma unroll
            for (int mi = 0; mi < 2; mi++) {
                uint32_t off = swz128((m0w + mi * 16 + a_r) * 128 + (kk + a_k) * 2);
                ldsm_x4(ah[mi][0], ah[mi][1], ah[mi][2], ah[mi][3], tAh + off);
                ldsm_x4(al[mi][0], al[mi][1], al[mi][2], al[mi][3], tAl + off);
            }
            #pragma unroll
            for (int hb = 0; hb < 2; hb++) {
                uint32_t off = swz128((n0w + hb * 16 + b_n) * 128 + (kk + b_k) * 2);
                ldsm_x4(bh[hb][0], bh[hb][1], bh[hb][2], bh[hb][3], tBh + off);
                ldsm_x4(bl[hb][0], bl[hb][1], bl[hb][2], bl[hb][3], tBl + off);
            }
            #pragma unroll
            for (int mi = 0; mi < 2; mi++)
                #pragma unroll
                for (int ni = 0; ni < 4; ni++) {
                    uint32_t b0h = bh[ni >> 1][(ni & 1) * 2];
                    uint32_t b1h = bh[ni >> 1][(ni & 1) * 2 + 1];
                    uint32_t b0l = bl[ni >> 1][(ni & 1) * 2];
                    uint32_t b1l = bl[ni >> 1][(ni & 1) * 2 + 1];
                    float* cc = acc[mi][ni];
                    mma_bf16(cc[0], cc[1], cc[2], cc[3],
                             ah[mi][0], ah[mi][1], ah[mi][2], ah[mi][3], b0h, b1h);
                    mma_bf16(cc[0], cc[1], cc[2], cc[3],
                             ah[mi][0], ah[mi][1], ah[mi][2], ah[mi][3], b0l, b1l);
                    mma_bf16(cc[0], cc[1], cc[2], cc[3],
                             al[mi][0], al[mi][1], al[mi][2], al[mi][3], b0h, b1h);
                }
        }
        __syncthreads();
    }

    // epilogue: raw accumulators -> contiguous staging rows (no atomics)
    const int cloc = n0w + (lane & 3) * 2;
    #pragma unroll
    for (int mi = 0; mi < 2; mi++) {
        #pragma unroll
        for (int half = 0; half < 2; half++) {
            const int rloc = m0w + mi * 16 + (lane >> 2) + half * 8;
            const int r = row0 + rloc;
            if (r < cnt) {
                float* yrow = g_y + (size_t)(ybase + r) * TD + col0;
                #pragma unroll
                for (int ni = 0; ni < 4; ni++) {
                    float2 v = make_float2(acc[mi][ni][half * 2 + 0],
                                           acc[mi][ni][half * 2 + 1]);
                    *(float2*)(yrow + cloc + ni * 8) = v;
                }
            }
        }
    }
}

// ---------------- combine: staging -> output rows (+relu split for next) ----
__global__ void __launch_bounds__(256) combine_kernel(
    const float* __restrict__ bias, const float* __restrict__ ca,
    const float* __restrict__ temp, float* __restrict__ out, int make_split) {
    __shared__ float s_ia[TE];
    const int tid = threadIdx.x;
    if (tid < TE) s_ia[tid] = expf(fminf(ca[tid], LOG100));
    // fold next-layer router reset into layer-0 combine
    if (make_split && blockIdx.x == 0) {
        if (tid < TE) { g_cnt[tid] = 0; g_imp[tid] = 0.0f; }
        if (tid == TE) g_vq[0] = 0.0f;
    }
    __syncthreads();
    const float temp_s = expf(fminf(temp[0], LOG100));

    const int tok = blockIdx.x * 8 + (tid >> 5);
    const int lane = tid & 31;

    const int e0 = g_te0[tok], e1 = g_te1[tok];
    const float tv0 = g_tv0[tok] * temp_s, tv1 = g_tv1[tok] * temp_s;
    const float ia0 = s_ia[e0], ia1 = s_ia[e1];
    const float4* y0 = (const float4*)(g_y + (size_t)(g_base[e0] + g_tp0[tok]) * TD);
    const float4* y1 = (const float4*)(g_y + (size_t)(g_base[e1] + g_tp1[tok]) * TD);
    const float4* b0 = (const float4*)(bias + e0 * TD);
    const float4* b1 = (const float4*)(bias + e1 * TD);
    float4* orow = (float4*)(out + (size_t)tok * TD);
    __nv_bfloat162* hrow = (__nv_bfloat162*)(g_ah + (size_t)tok * TD);
    __nv_bfloat162* lrow = (__nv_bfloat162*)(g_al + (size_t)tok * TD);

    #pragma unroll
    for (int j = 0; j < 4; j++) {
        const int idx = lane + 32 * j;
        float4 a = y0[idx], b = y1[idx], p = b0[idx], q = b1[idx];
        float4 o;
        o.x = tv0 * fmaf(a.x, ia0, p.x) + tv1 * fmaf(b.x, ia1, q.x);
        o.y = tv0 * fmaf(a.y, ia0, p.y) + tv1 * fmaf(b.y, ia1, q.y);
        o.z = tv0 * fmaf(a.z, ia0, p.z) + tv1 * fmaf(b.z, ia1, q.z);
        o.w = tv0 * fmaf(a.w, ia0, p.w) + tv1 * fmaf(b.w, ia1, q.w);
        orow[idx] = o;
        if (make_split) {
            float rx = fmaxf(o.x, 0.f), ry = fmaxf(o.y, 0.f);
            float rz = fmaxf(o.z, 0.f), rw = fmaxf(o.w, 0.f);
            __nv_bfloat16 hx = __float2bfloat16(rx), hy = __float2bfloat16(ry);
            __nv_bfloat16 hz = __float2bfloat16(rz), hw = __float2bfloat16(rw);
            hrow[2 * idx]     = __nv_bfloat162(hx, hy);
            hrow[2 * idx + 1] = __nv_bfloat162(hz, hw);
            lrow[2 * idx]     = __nv_bfloat162(__float2bfloat16(rx - __bfloat162float(hx)),
                                               __float2bfloat16(ry - __bfloat162float(hy)));
            lrow[2 * idx + 1] = __nv_bfloat162(__float2bfloat16(rz - __bfloat162float(hz)),
                                               __float2bfloat16(rw - __bfloat162float(hw)));
        }
    }
}

// ---------------- final aux write ----------------
__global__ void write_aux_kernel(float* __restrict__ out) {
    if (threadIdx.x == 0 && blockIdx.x == 0)
        out[(size_t)2 * TB * TD] = g_aux[0] + g_aux[1];
}

// ---------------- launch ----------------
extern "C" void kernel_launch(void* const* d_in, const int* in_sizes, int n_in,
                              void* d_out, int out_size) {
    const float* x   = (const float*)d_in[0];
    const float* rm0 = (const float*)d_in[1];
    const float* W0  = (const float*)d_in[2];
    const float* b0  = (const float*)d_in[3];
    const float* t0  = (const float*)d_in[4];
    const float* ca0 = (const float*)d_in[5];
    const float* rm1 = (const float*)d_in[6];
    const float* W1  = (const float*)d_in[7];
    const float* b1  = (const float*)d_in[8];
    const float* t1  = (const float*)d_in[9];
    const float* ca1 = (const float*)d_in[10];

    float* out = (float*)d_out;
    float* h0 = out;                      // h_emb region
    float* h1 = out + (size_t)TB * TD;    // h1 region

    cudaFuncSetAttribute(gemm_mma_kernel,
                         cudaFuncAttributeMaxDynamicSharedMemorySize,
                         GEMM_SMEM_BYTES);

    __nv_bfloat16* ah = nullptr, *al = nullptr, *bh = nullptr, *bl = nullptr;
    cudaGetSymbolAddress((void**)&ah, g_ah);
    cudaGetSymbolAddress((void**)&al, g_al);
    cudaGetSymbolAddress((void**)&bh, g_bh);
    cudaGetSymbolAddress((void**)&bl, g_bl);

    const int nX4 = TB * TD / 4;
    const int nW4 = TE * TD * TD / 4;
    dim3 gg(TD / 128, TB / 128, TE);

    // ---- layer 0 ----
    zero_small_kernel<<<1, 32>>>();
    router_kernel<<<TB / 8, 256>>>(x, rm0, 0);
    finalize_kernel<<<1, 32>>>(0);
    conv_split_kernel<<<(nX4 + 255) / 256, 256>>>((const float4*)x,
        (__nv_bfloat162*)ah, (__nv_bfloat162*)al, nX4);
    conv_split_kernel<<<(nW4 + 255) / 256, 256>>>((const float4*)W0,
        (__nv_bfloat162*)bh, (__nv_bfloat162*)bl, nW4);
    gemm_mma_kernel<<<gg, 512, GEMM_SMEM_BYTES>>>();
    combine_kernel<<<TB / 8, 256>>>(b0, ca0, t0, h0, 1);  // also resets router state

    // ---- layer 1 ----
    router_kernel<<<TB / 8, 256>>>(h0, rm1, 1);
    finalize_kernel<<<1, 32>>>(1);
    conv_split_kernel<<<(nW4 + 255) / 256, 256>>>((const float4*)W1,
        (__nv_bfloat162*)bh, (__nv_bfloat162*)bl, nW4);
    gemm_mma_kernel<<<gg, 512, GEMM_SMEM_BYTES>>>();
    combine_kernel<<<TB / 8, 256>>>(b1, ca1, t1, h1, 0);

    write_aux_kernel<<<1, 1>>>(out);
}

// round 5
// speedup vs baseline: 1.4740x; 1.0403x over previous
#include <cuda_runtime.h>
#include <cuda_bf16.h>
#include <math.h>
#include <stdint.h>

#define TB 16384      // batch
#define TD 512        // dim (in = hid = out)
#define TE 8          // experts
#define LOG100 4.605170185988091f

// ---------------- device scratch (per-layer router state) ----------------
__device__ int   g_cnt[2][TE];
__device__ int   g_list[2][TE * TB];
__device__ float g_imp[2][TE];
__device__ float g_vq[2];
// per-token routing meta (per layer)
__device__ int   g_te0[2][TB], g_te1[2][TB];
__device__ int   g_tp0[2][TB], g_tp1[2][TB];
__device__ float g_tv0[2][TB], g_tv1[2][TB];
// staging: raw GEMM accumulators, rows ordered by (expert, position)
__device__ float g_y[2 * TB * TD];
// bf16 split buffers: A (x or relu(h0)), W for BOTH layers
__device__ __nv_bfloat16 g_ah[TB * TD];
__device__ __nv_bfloat16 g_al[TB * TD];
__device__ __nv_bfloat16 g_bh[2 * TE * TD * TD];
__device__ __nv_bfloat16 g_bl[2 * TE * TD * TD];

// ---------------- helpers ----------------
__device__ __forceinline__ uint32_t smem_u32(const void* p) {
    uint32_t a;
    asm("{ .reg .u64 t; cvta.to.shared.u64 t, %1; cvt.u32.u64 %0, t; }" : "=r"(a) : "l"(p));
    return a;
}
__device__ __forceinline__ uint32_t swz128(uint32_t off) {
    return off ^ ((off >> 3) & 0x70);
}
__device__ __forceinline__ void cp16(uint32_t saddr, const void* gaddr) {
    asm volatile("cp.async.cg.shared.global [%0], [%1], 16;" :: "r"(saddr), "l"(gaddr));
}
__device__ __forceinline__ void cp_commit() {
    asm volatile("cp.async.commit_group;");
}
__device__ __forceinline__ void cp_wait1() {
    asm volatile("cp.async.wait_group 1;");
}
__device__ __forceinline__ void ldsm_x4(uint32_t& r0, uint32_t& r1, uint32_t& r2,
                                        uint32_t& r3, uint32_t addr) {
    asm volatile("ldmatrix.sync.aligned.m8n8.x4.shared.b16 {%0,%1,%2,%3}, [%4];"
                 : "=r"(r0), "=r"(r1), "=r"(r2), "=r"(r3) : "r"(addr));
}
__device__ __forceinline__ void mma_bf16(float& c0, float& c1, float& c2, float& c3,
                                         uint32_t a0, uint32_t a1, uint32_t a2, uint32_t a3,
                                         uint32_t b0, uint32_t b1) {
    asm volatile(
        "mma.sync.aligned.m16n8k16.row.col.f32.bf16.bf16.f32 "
        "{%0,%1,%2,%3}, {%4,%5,%6,%7}, {%8,%9}, {%0,%1,%2,%3};"
        : "+f"(c0), "+f"(c1), "+f"(c2), "+f"(c3)
        : "r"(a0), "r"(a1), "r"(a2), "r"(a3), "r"(b0), "r"(b1));
}
__device__ __forceinline__ void split4(float4 a, __nv_bfloat162* hi2, __nv_bfloat162* lo2) {
    __nv_bfloat16 hx = __float2bfloat16(a.x), hy = __float2bfloat16(a.y);
    __nv_bfloat16 hz = __float2bfloat16(a.z), hw = __float2bfloat16(a.w);
    hi2[0] = __nv_bfloat162(hx, hy);
    hi2[1] = __nv_bfloat162(hz, hw);
    lo2[0] = __nv_bfloat162(__float2bfloat16(a.x - __bfloat162float(hx)),
                            __float2bfloat16(a.y - __bfloat162float(hy)));
    lo2[1] = __nv_bfloat162(__float2bfloat16(a.z - __bfloat162float(hz)),
                            __float2bfloat16(a.w - __bfloat162float(hw)));
}

// ---------------- conv X (layer 0) + reset all per-run router state ----------
__global__ void __launch_bounds__(256) convx_kernel(const float4* __restrict__ src) {
    if (blockIdx.x == 0 && threadIdx.x < 2 * TE) {
        int l = threadIdx.x / TE, e = threadIdx.x % TE;
        g_cnt[l][e] = 0; g_imp[l][e] = 0.0f;
        if (e == 0) g_vq[l] = 0.0f;
    }
    int i = blockIdx.x * blockDim.x + threadIdx.x;
    if (i >= TB * TD / 4) return;
    float4 a = src[i];
    split4(a, (__nv_bfloat162*)g_ah + 2 * i, (__nv_bfloat162*)g_al + 2 * i);
}

// ---------------- conv W (both layers) ----------------
__global__ void __launch_bounds__(256) convw_kernel(const float4* __restrict__ W0,
                                                    const float4* __restrict__ W1) {
    const int n4 = TE * TD * TD / 4;
    int i = blockIdx.x * blockDim.x + threadIdx.x;
    if (i < n4) {
        split4(W0[i], (__nv_bfloat162*)g_bh + 2 * i, (__nv_bfloat162*)g_bl + 2 * i);
    } else {
        int j = i - n4;
        split4(W1[j], (__nv_bfloat162*)g_bh + 2 * (n4 + j),
                      (__nv_bfloat162*)g_bl + 2 * (n4 + j));
    }
}

// ---------------- router ----------------
__global__ void __launch_bounds__(256) router_kernel(const float* __restrict__ x,
                                                     const float* __restrict__ rm,
                                                     int layer, int relu_in) {
    __shared__ float s_rm[TE][TD];
    __shared__ float s_rmn[TE];
    const int tid = threadIdx.x;
    for (int i = tid; i < TE * TD; i += 256) s_rm[i >> 9][i & 511] = rm[i];
    __syncthreads();

    const int w = tid >> 5;
    const int lane = tid & 31;

    {
        float s = 0.0f;
        #pragma unroll
        for (int j = 0; j < 16; j++) { float v = s_rm[w][lane + 32 * j]; s += v * v; }
        #pragma unroll
        for (int o = 16; o > 0; o >>= 1) s += __shfl_xor_sync(0xffffffffu, s, o);
        if (lane == 0) s_rmn[w] = fmaxf(sqrtf(s), 1e-12f);
    }
    __syncthreads();

    const int b = blockIdx.x * 8 + w;
    float xx = 0.0f, dot[TE];
    #pragma unroll
    for (int e = 0; e < TE; e++) dot[e] = 0.0f;
    const float* xr = x + (size_t)b * TD;
    #pragma unroll
    for (int j = 0; j < 16; j++) {
        float xv = xr[lane + 32 * j];
        if (relu_in) xv = fmaxf(xv, 0.0f);
        xx = fmaf(xv, xv, xx);
        #pragma unroll
        for (int e = 0; e < TE; e++) dot[e] = fmaf(xv, s_rm[e][lane + 32 * j], dot[e]);
    }
    #pragma unroll
    for (int o = 16; o > 0; o >>= 1) {
        xx += __shfl_xor_sync(0xffffffffu, xx, o);
        #pragma unroll
        for (int e = 0; e < TE; e++) dot[e] += __shfl_xor_sync(0xffffffffu, dot[e], o);
    }

    if (lane == 0) {
        float xn = fmaxf(sqrtf(xx), 1e-12f);
        float d[TE];
        #pragma unroll
        for (int e = 0; e < TE; e++) d[e] = dot[e] / (xn * s_rmn[e]);

        int i0 = 0; float v0 = d[0];
        #pragma unroll
        for (int e = 1; e < TE; e++) if (d[e] > v0) { v0 = d[e]; i0 = e; }
        int i1 = (i0 == 0) ? 1 : 0; float v1 = d[i1];
        #pragma unroll
        for (int e = 0; e < TE; e++) {
            if (e != i0 && d[e] > v1) { v1 = d[e]; i1 = e; }
        }
        float e1 = expf(v1 - v0);
        float inv = 1.0f / (1.0f + e1);
        float tv0 = inv;
        float tv1 = e1 * inv;

        int p0 = atomicAdd(&g_cnt[layer][i0], 1);
        g_list[layer][i0 * TB + p0] = b;
        int p1 = atomicAdd(&g_cnt[layer][i1], 1);
        g_list[layer][i1 * TB + p1] = b;

        g_te0[layer][b] = i0; g_te1[layer][b] = i1;
        g_tp0[layer][b] = p0; g_tp1[layer][b] = p1;
        g_tv0[layer][b] = tv0; g_tv1[layer][b] = tv1;

        atomicAdd(&g_imp[layer][i0], tv0);
        atomicAdd(&g_imp[layer][i1], tv1);
        atomicAdd(&g_vq[layer], -(tv0 * v0 + tv1 * v1));
    }
}

// ---------------- mma.sync grouped gather-GEMM -> staging ----------------
// 128x128 tile, 512 threads (16 warps, 4x4), warp tile 32x32, K-chunk 64,
// 3-stage cp.async pipeline, single __syncthreads per chunk.
#define GEMM_SMEM_BYTES (1024 + 3 * 4 * 16384)

__global__ void __launch_bounds__(512, 1)
gemm_mma_kernel(int layer) {
    const int e = blockIdx.z;
    const int cnt = g_cnt[layer][e];
    const int row0 = blockIdx.y * 128;
    if (row0 >= cnt) return;
    const int col0 = blockIdx.x * 128;
    int ybase = 0;
    #pragma unroll
    for (int q = 0; q < TE; q++) if (q < e) ybase += g_cnt[layer][q];

    extern __shared__ char smem[];
    const uint32_t sbase = smem_u32(smem);
    int* s_row = (int*)(smem + 16);
    const int tid = threadIdx.x;

    if (tid < 128) {
        int r = row0 + tid;
        s_row[tid] = (r < cnt) ? g_list[layer][e * TB + r] : 0;
    }
    __syncthreads();

    // loader: 512 threads = 4 tiles x 128 rows
    const int lt = tid >> 7;       // 0:Ah 1:Al 2:Bh 3:Bl
    const int lr = tid & 127;
    const size_t woff = (size_t)layer * TE * TD * TD + ((size_t)e * TD + col0 + lr) * TD;
    const __nv_bfloat16* lsrc;
    if (lt == 0)      lsrc = g_ah + (size_t)s_row[lr] * TD;
    else if (lt == 1) lsrc = g_al + (size_t)s_row[lr] * TD;
    else if (lt == 2) lsrc = g_bh + woff;
    else              lsrc = g_bl + woff;
    uint32_t lsw[8];
    #pragma unroll
    for (int j = 0; j < 8; j++) lsw[j] = swz128(lr * 128 + j * 16);
    const uint32_t ltile = sbase + 1024 + lt * 16384;

    auto issue = [&](int c) {
        const uint32_t sb = ltile + (c % 3) * 65536;
        const char* gp = (const char*)lsrc + c * 128;
        #pragma unroll
        for (int j = 0; j < 8; j++) cp16(sb + lsw[j], gp + j * 16);
        cp_commit();
    };

    const int warp = tid >> 5;
    const int lane = tid & 31;
    const int m0w = (warp >> 2) * 32;
    const int n0w = (warp & 3) * 32;

    const int a_r = lane & 15;
    const int a_k = (lane >> 4) << 3;
    const int b_idx = lane & 7;
    const int b_sel = lane >> 3;
    const int b_n = ((b_sel >> 1) << 3) + b_idx;
    const int b_k = (b_sel & 1) << 3;

    float acc[2][4][4];
    #pragma unroll
    for (int mi = 0; mi < 2; mi++)
        #pragma unroll
        for (int ni = 0; ni < 4; ni++)
            #pragma unroll
            for (int q = 0; q < 4; q++) acc[mi][ni][q] = 0.0f;

    issue(0);
    issue(1);

    for (int c = 0; c < 8; c++) {
        cp_wait1();            // chunk c resident (c+1 may still be in flight)
        __syncthreads();       // all warps done with buffer (c-1)%3 reads; c visible
        if (c + 2 < 8) issue(c + 2);

        const uint32_t base = sbase + 1024 + (c % 3) * 65536;
        const uint32_t tAh = base, tAl = base + 16384;
        const uint32_t tBh = base + 32768, tBl = base + 49152;

        #pragma unroll
        for (int ks = 0; ks < 4; ks++) {
            const int kk = ks * 16;
            uint32_t ah[2][4], al[2][4], bh[2][4], bl[2][4];
            #pragma unroll
            for (int mi = 0; mi < 2; mi++) {
                uint32_t off = swz128((m0w + mi * 16 + a_r) * 128 + (kk + a_k) * 2);
                ldsm_x4(ah[mi][0], ah[mi][1], ah[mi][2], ah[mi][3], tAh + off);
                ldsm_x4(al[mi][0], al[mi][1], al[mi][2], al[mi][3], tAl + off);
            }
            #pragma unroll
            for (int hb = 0; hb < 2; hb++) {
                uint32_t off = swz128((n0w + hb * 16 + b_n) * 128 + (kk + b_k) * 2);
                ldsm_x4(bh[hb][0], bh[hb][1], bh[hb][2], bh[hb][3], tBh + off);
                ldsm_x4(bl[hb][0], bl[hb][1], bl[hb][2], bl[hb][3], tBl + off);
            }
            #pragma unroll
            for (int mi = 0; mi < 2; mi++)
                #pragma unroll
                for (int ni = 0; ni < 4; ni++) {
                    uint32_t b0h = bh[ni >> 1][(ni & 1) * 2];
                    uint32_t b1h = bh[ni >> 1][(ni & 1) * 2 + 1];
                    uint32_t b0l = bl[ni >> 1][(ni & 1) * 2];
                    uint32_t b1l = bl[ni >> 1][(ni & 1) * 2 + 1];
                    float* cc = acc[mi][ni];
                    mma_bf16(cc[0], cc[1], cc[2], cc[3],
                             ah[mi][0], ah[mi][1], ah[mi][2], ah[mi][3], b0h, b1h);
                    mma_bf16(cc[0], cc[1], cc[2], cc[3],
                             ah[mi][0], ah[mi][1], ah[mi][2], ah[mi][3], b0l, b1l);
                    mma_bf16(cc[0], cc[1], cc[2], cc[3],
                             al[mi][0], al[mi][1], al[mi][2], al[mi][3], b0h, b1h);
                }
        }
    }

    // epilogue: raw accumulators -> contiguous staging rows
    const int cloc = n0w + (lane & 3) * 2;
    #pragma unroll
    for (int mi = 0; mi < 2; mi++) {
        #pragma unroll
        for (int half = 0; half < 2; half++) {
            const int rloc = m0w + mi * 16 + (lane >> 2) + half * 8;
            const int r = row0 + rloc;
            if (r < cnt) {
                float* yrow = g_y + (size_t)(ybase + r) * TD + col0;
                #pragma unroll
                for (int ni = 0; ni < 4; ni++) {
                    float2 v = make_float2(acc[mi][ni][half * 2 + 0],
                                           acc[mi][ni][half * 2 + 1]);
                    *(float2*)(yrow + cloc + ni * 8) = v;
                }
            }
        }
    }
}

// ---------------- combine: staging -> output rows (+relu split for next) ----
__global__ void __launch_bounds__(256) combine_kernel(
    const float* __restrict__ bias, const float* __restrict__ ca,
    const float* __restrict__ temp, float* __restrict__ out,
    int layer, int make_split) {
    __shared__ float s_ia[TE];
    __shared__ int s_base[TE];
    const int tid = threadIdx.x;
    if (tid < TE) {
        s_ia[tid] = expf(fminf(ca[tid], LOG100));
        int acc = 0;
        #pragma unroll
        for (int q = 0; q < TE; q++) if (q < tid) acc += g_cnt[layer][q];
        s_base[tid] = acc;
    }
    __syncthreads();
    const float temp_s = expf(fminf(temp[0], LOG100));

    const int tok = blockIdx.x * 8 + (tid >> 5);
    const int lane = tid & 31;

    const int e0 = g_te0[layer][tok], e1 = g_te1[layer][tok];
    const float tv0 = g_tv0[layer][tok] * temp_s, tv1 = g_tv1[layer][tok] * temp_s;
    const float ia0 = s_ia[e0], ia1 = s_ia[e1];
    const float4* y0 = (const float4*)(g_y + (size_t)(s_base[e0] + g_tp0[layer][tok]) * TD);
    const float4* y1 = (const float4*)(g_y + (size_t)(s_base[e1] + g_tp1[layer][tok]) * TD);
    const float4* b0 = (const float4*)(bias + e0 * TD);
    const float4* b1 = (const float4*)(bias + e1 * TD);
    float4* orow = (float4*)(out + (size_t)tok * TD);
    __nv_bfloat162* hrow = (__nv_bfloat162*)(g_ah + (size_t)tok * TD);
    __nv_bfloat162* lrow = (__nv_bfloat162*)(g_al + (size_t)tok * TD);

    #pragma unroll
    for (int j = 0; j < 4; j++) {
        const int idx = lane + 32 * j;
        float4 a = y0[idx], b = y1[idx], p = b0[idx], q = b1[idx];
        float4 o;
        o.x = tv0 * fmaf(a.x, ia0, p.x) + tv1 * fmaf(b.x, ia1, q.x);
        o.y = tv0 * fmaf(a.y, ia0, p.y) + tv1 * fmaf(b.y, ia1, q.y);
        o.z = tv0 * fmaf(a.z, ia0, p.z) + tv1 * fmaf(b.z, ia1, q.z);
        o.w = tv0 * fmaf(a.w, ia0, p.w) + tv1 * fmaf(b.w, ia1, q.w);
        orow[idx] = o;
        if (make_split) {
            float4 r4 = make_float4(fmaxf(o.x, 0.f), fmaxf(o.y, 0.f),
                                    fmaxf(o.z, 0.f), fmaxf(o.w, 0.f));
            split4(r4, hrow + 2 * idx, lrow + 2 * idx);
        }
    }
}

// ---------------- final aux write (both layers) ----------------
__global__ void write_aux_kernel(float* __restrict__ out) {
    if (threadIdx.x == 0 && blockIdx.x == 0) {
        float aux = 0.0f;
        for (int l = 0; l < 2; l++) {
            float m = 0.0f;
            for (int e = 0; e < TE; e++) m += g_imp[l][e];
            m *= (1.0f / TE);
            float var = 0.0f;
            for (int e = 0; e < TE; e++) { float dd = g_imp[l][e] - m; var += dd * dd; }
            var *= (1.0f / (TE - 1));
            float lb = var / (m * m + 1e-10f);
            aux += 0.05f * (g_vq[l] * (1.0f / TB)) + 0.01f * lb;
        }
        out[(size_t)2 * TB * TD] = aux;
    }
}

// ---------------- launch ----------------
extern "C" void kernel_launch(void* const* d_in, const int* in_sizes, int n_in,
                              void* d_out, int out_size) {
    const float* x   = (const float*)d_in[0];
    const float* rm0 = (const float*)d_in[1];
    const float* W0  = (const float*)d_in[2];
    const float* b0  = (const float*)d_in[3];
    const float* t0  = (const float*)d_in[4];
    const float* ca0 = (const float*)d_in[5];
    const float* rm1 = (const float*)d_in[6];
    const float* W1  = (const float*)d_in[7];
    const float* b1  = (const float*)d_in[8];
    const float* t1  = (const float*)d_in[9];
    const float* ca1 = (const float*)d_in[10];

    float* out = (float*)d_out;
    float* h0 = out;                      // h_emb region
    float* h1 = out + (size_t)TB * TD;    // h1 region

    cudaFuncSetAttribute(gemm_mma_kernel,
                         cudaFuncAttributeMaxDynamicSharedMemorySize,
                         GEMM_SMEM_BYTES);

    const int nX4 = TB * TD / 4;
    const int nW4 = TE * TD * TD / 4;
    dim3 gg(TD / 128, TB / 128, TE);

    // launch #0..#2: conversions + router (gemm lands at #3 for ncu)
    convx_kernel<<<(nX4 + 255) / 256, 256>>>((const float4*)x);
    convw_kernel<<<(2 * nW4 + 255) / 256, 256>>>((const float4*)W0, (const float4*)W1);
    router_kernel<<<TB / 8, 256>>>(x, rm0, 0, 0);
    gemm_mma_kernel<<<gg, 512, GEMM_SMEM_BYTES>>>(0);            // launch #3
    combine_kernel<<<TB / 8, 256>>>(b0, ca0, t0, h0, 0, 1);

    router_kernel<<<TB / 8, 256>>>(h0, rm1, 1, 1);
    gemm_mma_kernel<<<gg, 512, GEMM_SMEM_BYTES>>>(1);
    combine_kernel<<<TB / 8, 256>>>(b1, ca1, t1, h1, 1, 0);

    write_aux_kernel<<<1, 1>>>(out);
}

// round 6
// speedup vs baseline: 2.2684x; 1.5389x over previous
#include <cuda_runtime.h>
#include <cuda_bf16.h>
#include <math.h>
#include <stdint.h>

#define TB 16384      // batch
#define TD 512        // dim (in = hid = out)
#define TE 8          // experts
#define LOG100 4.605170185988091f

// ---------------- device scratch (per-layer router state) ----------------
__device__ int   g_cnt[2][TE];
__device__ int   g_list[2][TE * TB];
__device__ float g_imp[2][TE];
__device__ float g_vq[2];
// per-token routing meta (per layer)
__device__ int   g_te0[2][TB], g_te1[2][TB];
__device__ int   g_tp0[2][TB], g_tp1[2][TB];
__device__ float g_tv0[2][TB], g_tv1[2][TB];
// staging: raw GEMM accumulators, rows ordered by (expert, position)
__device__ float g_y[2 * TB * TD];
// bf16 split buffers: A (x or relu(h0)), W for BOTH layers
__device__ __nv_bfloat16 g_ah[TB * TD];
__device__ __nv_bfloat16 g_al[TB * TD];
__device__ __nv_bfloat16 g_bh[2 * TE * TD * TD];
__device__ __nv_bfloat16 g_bl[2 * TE * TD * TD];

// ---------------- helpers ----------------
__device__ __forceinline__ uint32_t smem_u32(const void* p) {
    uint32_t a;
    asm("{ .reg .u64 t; cvta.to.shared.u64 t, %1; cvt.u32.u64 %0, t; }" : "=r"(a) : "l"(p));
    return a;
}
__device__ __forceinline__ uint32_t swz128(uint32_t off) {
    return off ^ ((off >> 3) & 0x70);
}
__device__ __forceinline__ void cp16(uint32_t saddr, const void* gaddr) {
    asm volatile("cp.async.cg.shared.global [%0], [%1], 16;" :: "r"(saddr), "l"(gaddr));
}
__device__ __forceinline__ void cp_commit() {
    asm volatile("cp.async.commit_group;");
}
__device__ __forceinline__ void cp_wait0() {
    asm volatile("cp.async.wait_group 0;");
}
__device__ __forceinline__ void ldsm_x4(uint32_t& r0, uint32_t& r1, uint32_t& r2,
                                        uint32_t& r3, uint32_t addr) {
    asm volatile("ldmatrix.sync.aligned.m8n8.x4.shared.b16 {%0,%1,%2,%3}, [%4];"
                 : "=r"(r0), "=r"(r1), "=r"(r2), "=r"(r3) : "r"(addr));
}
__device__ __forceinline__ void mma_bf16(float& c0, float& c1, float& c2, float& c3,
                                         uint32_t a0, uint32_t a1, uint32_t a2, uint32_t a3,
                                         uint32_t b0, uint32_t b1) {
    asm volatile(
        "mma.sync.aligned.m16n8k16.row.col.f32.bf16.bf16.f32 "
        "{%0,%1,%2,%3}, {%4,%5,%6,%7}, {%8,%9}, {%0,%1,%2,%3};"
        : "+f"(c0), "+f"(c1), "+f"(c2), "+f"(c3)
        : "r"(a0), "r"(a1), "r"(a2), "r"(a3), "r"(b0), "r"(b1));
}
__device__ __forceinline__ void split4(float4 a, __nv_bfloat162* hi2, __nv_bfloat162* lo2) {
    __nv_bfloat16 hx = __float2bfloat16(a.x), hy = __float2bfloat16(a.y);
    __nv_bfloat16 hz = __float2bfloat16(a.z), hw = __float2bfloat16(a.w);
    hi2[0] = __nv_bfloat162(hx, hy);
    hi2[1] = __nv_bfloat162(hz, hw);
    lo2[0] = __nv_bfloat162(__float2bfloat16(a.x - __bfloat162float(hx)),
                            __float2bfloat16(a.y - __bfloat162float(hy)));
    lo2[1] = __nv_bfloat162(__float2bfloat16(a.z - __bfloat162float(hz)),
                            __float2bfloat16(a.w - __bfloat162float(hw)));
}

// ---------------- conv X (layer 0) + reset all per-run router state ----------
__global__ void __launch_bounds__(256) convx_kernel(const float4* __restrict__ src) {
    if (blockIdx.x == 0 && threadIdx.x < 2 * TE) {
        int l = threadIdx.x / TE, e = threadIdx.x % TE;
        g_cnt[l][e] = 0; g_imp[l][e] = 0.0f;
        if (e == 0) g_vq[l] = 0.0f;
    }
    int i = blockIdx.x * blockDim.x + threadIdx.x;
    if (i >= TB * TD / 4) return;
    float4 a = src[i];
    split4(a, (__nv_bfloat162*)g_ah + 2 * i, (__nv_bfloat162*)g_al + 2 * i);
}

// ---------------- conv W (both layers) ----------------
__global__ void __launch_bounds__(256) convw_kernel(const float4* __restrict__ W0,
                                                    const float4* __restrict__ W1) {
    const int n4 = TE * TD * TD / 4;
    int i = blockIdx.x * blockDim.x + threadIdx.x;
    if (i < n4) {
        split4(W0[i], (__nv_bfloat162*)g_bh + 2 * i, (__nv_bfloat162*)g_bl + 2 * i);
    } else {
        int j = i - n4;
        split4(W1[j], (__nv_bfloat162*)g_bh + 2 * (n4 + j),
                      (__nv_bfloat162*)g_bl + 2 * (n4 + j));
    }
}

// ---------------- router ----------------
__global__ void __launch_bounds__(256) router_kernel(const float* __restrict__ x,
                                                     const float* __restrict__ rm,
                                                     int layer, int relu_in) {
    __shared__ float s_rm[TE][TD];
    __shared__ float s_rmn[TE];
    const int tid = threadIdx.x;
    for (int i = tid; i < TE * TD; i += 256) s_rm[i >> 9][i & 511] = rm[i];
    __syncthreads();

    const int w = tid >> 5;
    const int lane = tid & 31;

    {
        float s = 0.0f;
        #pragma unroll
        for (int j = 0; j < 16; j++) { float v = s_rm[w][lane + 32 * j]; s += v * v; }
        #pragma unroll
        for (int o = 16; o > 0; o >>= 1) s += __shfl_xor_sync(0xffffffffu, s, o);
        if (lane == 0) s_rmn[w] = fmaxf(sqrtf(s), 1e-12f);
    }
    __syncthreads();

    const int b = blockIdx.x * 8 + w;
    float xx = 0.0f, dot[TE];
    #pragma unroll
    for (int e = 0; e < TE; e++) dot[e] = 0.0f;
    const float* xr = x + (size_t)b * TD;
    #pragma unroll
    for (int j = 0; j < 16; j++) {
        float xv = xr[lane + 32 * j];
        if (relu_in) xv = fmaxf(xv, 0.0f);
        xx = fmaf(xv, xv, xx);
        #pragma unroll
        for (int e = 0; e < TE; e++) dot[e] = fmaf(xv, s_rm[e][lane + 32 * j], dot[e]);
    }
    #pragma unroll
    for (int o = 16; o > 0; o >>= 1) {
        xx += __shfl_xor_sync(0xffffffffu, xx, o);
        #pragma unroll
        for (int e = 0; e < TE; e++) dot[e] += __shfl_xor_sync(0xffffffffu, dot[e], o);
    }

    if (lane == 0) {
        float xn = fmaxf(sqrtf(xx), 1e-12f);
        float d[TE];
        #pragma unroll
        for (int e = 0; e < TE; e++) d[e] = dot[e] / (xn * s_rmn[e]);

        int i0 = 0; float v0 = d[0];
        #pragma unroll
        for (int e = 1; e < TE; e++) if (d[e] > v0) { v0 = d[e]; i0 = e; }
        int i1 = (i0 == 0) ? 1 : 0; float v1 = d[i1];
        #pragma unroll
        for (int e = 0; e < TE; e++) {
            if (e != i0 && d[e] > v1) { v1 = d[e]; i1 = e; }
        }
        float e1 = expf(v1 - v0);
        float inv = 1.0f / (1.0f + e1);
        float tv0 = inv;
        float tv1 = e1 * inv;

        int p0 = atomicAdd(&g_cnt[layer][i0], 1);
        g_list[layer][i0 * TB + p0] = b;
        int p1 = atomicAdd(&g_cnt[layer][i1], 1);
        g_list[layer][i1 * TB + p1] = b;

        g_te0[layer][b] = i0; g_te1[layer][b] = i1;
        g_tp0[layer][b] = p0; g_tp1[layer][b] = p1;
        g_tv0[layer][b] = tv0; g_tv1[layer][b] = tv1;

        atomicAdd(&g_imp[layer][i0], tv0);
        atomicAdd(&g_imp[layer][i1], tv1);
        atomicAdd(&g_vq[layer], -(tv0 * v0 + tv1 * v1));
    }
}

// ---------------- mma.sync grouped gather-GEMM -> staging ----------------
// 128(M) x 64(N) tile, 256 threads (8 warps = 4x2), warp tile 32x32,
// K-chunk 64, 2-stage cp.async pipeline, 2 CTAs/SM.
// Stage layout: Ah 16K | Al 16K | Bh 8K | Bl 8K = 48KB per stage.
#define STAGE_BYTES 49152
#define GEMM_SMEM_BYTES (1024 + 2 * STAGE_BYTES)

__global__ void __launch_bounds__(256, 2)
gemm_mma_kernel(int layer) {
    const int e = blockIdx.z;
    const int cnt = g_cnt[layer][e];
    const int row0 = blockIdx.y * 128;
    if (row0 >= cnt) return;
    const int col0 = blockIdx.x * 64;
    int ybase = 0;
    #pragma unroll
    for (int q = 0; q < TE; q++) if (q < e) ybase += g_cnt[layer][q];

    extern __shared__ char smem[];
    const uint32_t sbase = smem_u32(smem);
    int* s_row = (int*)(smem + 16);
    const int tid = threadIdx.x;

    if (tid < 128) {
        int r = row0 + tid;
        s_row[tid] = (r < cnt) ? g_list[layer][e * TB + r] : 0;
    }
    __syncthreads();

    // ---- loader precompute: 3072 cp16 ops, 12 per thread ----
    const size_t woff_base = (size_t)layer * TE * TD * TD + ((size_t)e * TD + col0) * TD;
    const char* gp[12];
    uint32_t so[12];
    #pragma unroll
    for (int j = 0; j < 12; j++) {
        int idx = tid + 256 * j;
        int r384 = idx >> 3, seg = idx & 7;
        const __nv_bfloat16* base;
        uint32_t tile_off;
        int rloc;
        if (r384 < 128)      { tile_off = 0;     rloc = r384;       base = g_ah + (size_t)s_row[rloc] * TD; }
        else if (r384 < 256) { tile_off = 16384; rloc = r384 - 128; base = g_al + (size_t)s_row[rloc] * TD; }
        else if (r384 < 320) { tile_off = 32768; rloc = r384 - 256; base = g_bh + woff_base + (size_t)rloc * TD; }
        else                 { tile_off = 40960; rloc = r384 - 320; base = g_bl + woff_base + (size_t)rloc * TD; }
        so[j] = tile_off + swz128(rloc * 128 + seg * 16);
        gp[j] = (const char*)base + seg * 16;
    }

    auto issue = [&](int c) {
        const uint32_t sb = sbase + 1024 + (c & 1) * STAGE_BYTES;
        const int koff = c * 128;
        #pragma unroll
        for (int j = 0; j < 12; j++) cp16(sb + so[j], gp[j] + koff);
        cp_commit();
    };

    // ---- compute mapping: 8 warps = 4(m) x 2(n), warp tile 32x32 ----
    const int warp = tid >> 5;
    const int lane = tid & 31;
    const int m0w = (warp >> 1) * 32;
    const int n0w = (warp & 1) * 32;

    const int a_r = lane & 15;
    const int a_k = (lane >> 4) << 3;
    const int b_idx = lane & 7;
    const int b_sel = lane >> 3;
    const int b_n = ((b_sel >> 1) << 3) + b_idx;
    const int b_k = (b_sel & 1) << 3;

    float acc[2][4][4];
    #pragma unroll
    for (int mi = 0; mi < 2; mi++)
        #pragma unroll
        for (int ni = 0; ni < 4; ni++)
            #pragma unroll
            for (int q = 0; q < 4; q++) acc[mi][ni][q] = 0.0f;

    issue(0);

    for (int c = 0; c < 8; c++) {
        cp_wait0();
        __syncthreads();      // chunk c visible; all warps done with buffer (c+1)&1
        if (c + 1 < 8) issue(c + 1);

        const uint32_t stg = sbase + 1024 + (c & 1) * STAGE_BYTES;
        const uint32_t tAh = stg, tAl = stg + 16384;
        const uint32_t tBh = stg + 32768, tBl = stg + 40960;

        #pragma unroll
        for (int ks = 0; ks < 4; ks++) {
            const int kk = ks * 16;
            uint32_t ah[2][4], al[2][4], bh[2][4], bl[2][4];
            #pragma unroll
            for (int mi = 0; mi < 2; mi++) {
                uint32_t off = swz128((m0w + mi * 16 + a_r) * 128 + (kk + a_k) * 2);
                ldsm_x4(ah[mi][0], ah[mi][1], ah[mi][2], ah[mi][3], tAh + off);
                ldsm_x4(al[mi][0], al[mi][1], al[mi][2], al[mi][3], tAl + off);
            }
            #pragma unroll
            for (int hb = 0; hb < 2; hb++) {
                uint32_t off = swz128((n0w + hb * 16 + b_n) * 128 + (kk + b_k) * 2);
                ldsm_x4(bh[hb][0], bh[hb][1], bh[hb][2], bh[hb][3], tBh + off);
                ldsm_x4(bl[hb][0], bl[hb][1], bl[hb][2], bl[hb][3], tBl + off);
            }
            // term-outermost: adjacent MMAs hit different accumulators
            #pragma unroll
            for (int t = 0; t < 3; t++) {
                #pragma unroll
                for (int mi = 0; mi < 2; mi++)
                    #pragma unroll
                    for (int ni = 0; ni < 4; ni++) {
                        const uint32_t* av = (t == 2) ? al[mi] : ah[mi];
                        const uint32_t* bv = (t == 1) ? bl[ni >> 1] : bh[ni >> 1];
                        float* cc = acc[mi][ni];
                        mma_bf16(cc[0], cc[1], cc[2], cc[3],
                                 av[0], av[1], av[2], av[3],
                                 bv[(ni & 1) * 2], bv[(ni & 1) * 2 + 1]);
                    }
            }
        }
    }

    // ---- epilogue: raw accumulators -> contiguous staging rows ----
    const int cloc = n0w + (lane & 3) * 2;
    #pragma unroll
    for (int mi = 0; mi < 2; mi++) {
        #pragma unroll
        for (int half = 0; half < 2; half++) {
            const int rloc = m0w + mi * 16 + (lane >> 2) + half * 8;
            const int r = row0 + rloc;
            if (r < cnt) {
                float* yrow = g_y + (size_t)(ybase + r) * TD + col0;
                #pragma unroll
                for (int ni = 0; ni < 4; ni++) {
                    float2 v = make_float2(acc[mi][ni][half * 2 + 0],
                                           acc[mi][ni][half * 2 + 1]);
                    *(float2*)(yrow + cloc + ni * 8) = v;
                }
            }
        }
    }
}

// ---------------- combine: staging -> output rows (+relu split for next) ----
__global__ void __launch_bounds__(256) combine_kernel(
    const float* __restrict__ bias, const float* __restrict__ ca,
    const float* __restrict__ temp, float* __restrict__ out,
    int layer, int make_split) {
    __shared__ float s_ia[TE];
    __shared__ int s_base[TE];
    const int tid = threadIdx.x;
    if (tid < TE) {
        s_ia[tid] = expf(fminf(ca[tid], LOG100));
        int acc = 0;
        #pragma unroll
        for (int q = 0; q < TE; q++) if (q < tid) acc += g_cnt[layer][q];
        s_base[tid] = acc;
    }
    __syncthreads();
    const float temp_s = expf(fminf(temp[0], LOG100));

    const int tok = blockIdx.x * 8 + (tid >> 5);
    const int lane = tid & 31;

    const int e0 = g_te0[layer][tok], e1 = g_te1[layer][tok];
    const float tv0 = g_tv0[layer][tok] * temp_s, tv1 = g_tv1[layer][tok] * temp_s;
    const float ia0 = s_ia[e0], ia1 = s_ia[e1];
    const float4* y0 = (const float4*)(g_y + (size_t)(s_base[e0] + g_tp0[layer][tok]) * TD);
    const float4* y1 = (const float4*)(g_y + (size_t)(s_base[e1] + g_tp1[layer][tok]) * TD);
    const float4* b0 = (const float4*)(bias + e0 * TD);
    const float4* b1 = (const float4*)(bias + e1 * TD);
    float4* orow = (float4*)(out + (size_t)tok * TD);
    __nv_bfloat162* hrow = (__nv_bfloat162*)(g_ah + (size_t)tok * TD);
    __nv_bfloat162* lrow = (__nv_bfloat162*)(g_al + (size_t)tok * TD);

    #pragma unroll
    for (int j = 0; j < 4; j++) {
        const int idx = lane + 32 * j;
        float4 a = y0[idx], b = y1[idx], p = b0[idx], q = b1[idx];
        float4 o;
        o.x = tv0 * fmaf(a.x, ia0, p.x) + tv1 * fmaf(b.x, ia1, q.x);
        o.y = tv0 * fmaf(a.y, ia0, p.y) + tv1 * fmaf(b.y, ia1, q.y);
        o.z = tv0 * fmaf(a.z, ia0, p.z) + tv1 * fmaf(b.z, ia1, q.z);
        o.w = tv0 * fmaf(a.w, ia0, p.w) + tv1 * fmaf(b.w, ia1, q.w);
        orow[idx] = o;
        if (make_split) {
            float4 r4 = make_float4(fmaxf(o.x, 0.f), fmaxf(o.y, 0.f),
                                    fmaxf(o.z, 0.f), fmaxf(o.w, 0.f));
            split4(r4, hrow + 2 * idx, lrow + 2 * idx);
        }
    }
}

// ---------------- final aux write (both layers) ----------------
__global__ void write_aux_kernel(float* __restrict__ out) {
    if (threadIdx.x == 0 && blockIdx.x == 0) {
        float aux = 0.0f;
        for (int l = 0; l < 2; l++) {
            float m = 0.0f;
            for (int e = 0; e < TE; e++) m += g_imp[l][e];
            m *= (1.0f / TE);
            float var = 0.0f;
            for (int e = 0; e < TE; e++) { float dd = g_imp[l][e] - m; var += dd * dd; }
            var *= (1.0f / (TE - 1));
            float lb = var / (m * m + 1e-10f);
            aux += 0.05f * (g_vq[l] * (1.0f / TB)) + 0.01f * lb;
        }
        out[(size_t)2 * TB * TD] = aux;
    }
}

// ---------------- launch ----------------
extern "C" void kernel_launch(void* const* d_in, const int* in_sizes, int n_in,
                              void* d_out, int out_size) {
    const float* x   = (const float*)d_in[0];
    const float* rm0 = (const float*)d_in[1];
    const float* W0  = (const float*)d_in[2];
    const float* b0  = (const float*)d_in[3];
    const float* t0  = (const float*)d_in[4];
    const float* ca0 = (const float*)d_in[5];
    const float* rm1 = (const float*)d_in[6];
    const float* W1  = (const float*)d_in[7];
    const float* b1  = (const float*)d_in[8];
    const float* t1  = (const float*)d_in[9];
    const float* ca1 = (const float*)d_in[10];

    float* out = (float*)d_out;
    float* h0 = out;                      // h_emb region
    float* h1 = out + (size_t)TB * TD;    // h1 region

    cudaFuncSetAttribute(gemm_mma_kernel,
                         cudaFuncAttributeMaxDynamicSharedMemorySize,
                         GEMM_SMEM_BYTES);

    const int nX4 = TB * TD / 4;
    const int nW4 = TE * TD * TD / 4;
    dim3 gg(TD / 64, TB / 128, TE);

    // launch #0..#2: conversions + router (gemm lands at #3 for ncu)
    convx_kernel<<<(nX4 + 255) / 256, 256>>>((const float4*)x);
    convw_kernel<<<(2 * nW4 + 255) / 256, 256>>>((const float4*)W0, (const float4*)W1);
    router_kernel<<<TB / 8, 256>>>(x, rm0, 0, 0);
    gemm_mma_kernel<<<gg, 256, GEMM_SMEM_BYTES>>>(0);            // launch #3
    combine_kernel<<<TB / 8, 256>>>(b0, ca0, t0, h0, 0, 1);

    router_kernel<<<TB / 8, 256>>>(h0, rm1, 1, 1);
    gemm_mma_kernel<<<gg, 256, GEMM_SMEM_BYTES>>>(1);
    combine_kernel<<<TB / 8, 256>>>(b1, ca1, t1, h1, 1, 0);

    write_aux_kernel<<<1, 1>>>(out);
}